// round 1
// baseline (speedup 1.0000x reference)
#include <cuda_runtime.h>

#define BB   2048
#define SS   512
#define HH   64
#define OUTN 12
#define BT   16           // batch per CTA
#define CTAS (BB / BT)    // 128
#define NTHR 128
#define XCH  128          // x staging chunk (timesteps)

typedef unsigned long long ull;

__device__ __forceinline__ ull pk2(float x, float y) {
    ull r; asm("mov.b64 %0, {%1, %2};" : "=l"(r) : "f"(x), "f"(y)); return r;
}
__device__ __forceinline__ void upk2(ull v, float& x, float& y) {
    asm("mov.b64 {%0, %1}, %2;" : "=f"(x), "=f"(y) : "l"(v));
}
__device__ __forceinline__ void fma2(ull& d, ull a, ull b) {
    asm("fma.rn.f32x2 %0, %1, %2, %0;" : "+l"(d) : "l"(a), "l"(b));
}

__device__ __forceinline__ float sigf(float x) {
    return __fdividef(1.f, 1.f + __expf(-x));
}
__device__ __forceinline__ float tanh_(float x) {
    return __fdividef(2.f, 1.f + __expf(-2.f * x)) - 1.f;
}

// 64-step MAC: a[g][p] += W[j][u].g * h[j][pair p], h rows batch-major (stride BT)
__device__ __forceinline__ void mac64(ull a[4][4], const float4* __restrict__ Wp,
                                      const float* __restrict__ hrow, int pb0) {
#pragma unroll 8
    for (int j = 0; j < 64; j++) {
        float4 w = Wp[j * 64];
        ulonglong2 ha = *(const ulonglong2*)(hrow + j * BT + pb0);
        ulonglong2 hb = *(const ulonglong2*)(hrow + j * BT + pb0 + 4);
        ull w0 = pk2(w.x, w.x), w1 = pk2(w.y, w.y);
        ull w2 = pk2(w.z, w.z), w3 = pk2(w.w, w.w);
        fma2(a[0][0], w0, ha.x); fma2(a[0][1], w0, ha.y);
        fma2(a[0][2], w0, hb.x); fma2(a[0][3], w0, hb.y);
        fma2(a[1][0], w1, ha.x); fma2(a[1][1], w1, ha.y);
        fma2(a[1][2], w1, hb.x); fma2(a[1][3], w1, hb.y);
        fma2(a[2][0], w2, ha.x); fma2(a[2][1], w2, ha.y);
        fma2(a[2][2], w2, hb.x); fma2(a[2][3], w2, hb.y);
        fma2(a[3][0], w3, ha.x); fma2(a[3][1], w3, ha.y);
        fma2(a[3][2], w3, hb.x); fma2(a[3][3], w3, hb.y);
    }
}

// i,f,g,o gates (as f32x2 pairs) -> update c[8], produce h[8]
__device__ __forceinline__ void cell_update(ull a[4][4], float c[8], float hv[8]) {
#pragma unroll
    for (int p = 0; p < 4; p++) {
        float i0, i1, f0, f1, g0, g1, o0, o1;
        upk2(a[0][p], i0, i1);
        upk2(a[1][p], f0, f1);
        upk2(a[2][p], g0, g1);
        upk2(a[3][p], o0, o1);
        int k = 2 * p;
        c[k]     = sigf(f0) * c[k]     + sigf(i0) * tanh_(g0);
        c[k + 1] = sigf(f1) * c[k + 1] + sigf(i1) * tanh_(g1);
        hv[k]     = sigf(o0) * tanh_(c[k]);
        hv[k + 1] = sigf(o1) * tanh_(c[k + 1]);
    }
}

__global__ void __launch_bounds__(NTHR, 1) lstm2_kernel(
    const float* __restrict__ x,
    const float* __restrict__ w_ih0, const float* __restrict__ w_hh0,
    const float* __restrict__ b_ih0, const float* __restrict__ b_hh0,
    const float* __restrict__ w_ih1, const float* __restrict__ w_hh1,
    const float* __restrict__ b_ih1, const float* __restrict__ b_hh1,
    const float* __restrict__ fc_w, const float* __restrict__ fc_b,
    float* __restrict__ out)
{
    extern __shared__ float sm[];
    float4* W0 = (float4*)sm;            // [64 j][64 u] gate-packed Whh0
    float4* W1 = W0 + 64 * 64;           // Wih1
    float4* W2 = W1 + 64 * 64;           // Whh1
    float* h0s = (float*)(W2 + 64 * 64); // [2][64 u][BT b]
    float* h1s = h0s + 2 * 64 * BT;      // [2][64 u][BT b]
    float* xs  = h1s + 2 * 64 * BT;      // [XCH][BT]

    const int tid = threadIdx.x;
    const int u   = tid & 63;    // hidden unit owned by this thread
    const int pg  = tid >> 6;    // pair group 0..1
    const int pb0 = pg * 8;      // first batch (within tile) of this thread
    const int b0  = blockIdx.x * BT;

    // ---- stage gate-interleaved transposed weights into shared ----
    for (int e = tid; e < 64 * 64; e += NTHR) {
        int j = e & 63, uu = e >> 6;  // consecutive lanes -> consecutive j (coalesced LDG)
        W0[j * 64 + uu] = make_float4(w_hh0[uu * 64 + j],         w_hh0[(64 + uu) * 64 + j],
                                      w_hh0[(128 + uu) * 64 + j], w_hh0[(192 + uu) * 64 + j]);
        W1[j * 64 + uu] = make_float4(w_ih1[uu * 64 + j],         w_ih1[(64 + uu) * 64 + j],
                                      w_ih1[(128 + uu) * 64 + j], w_ih1[(192 + uu) * 64 + j]);
        W2[j * 64 + uu] = make_float4(w_hh1[uu * 64 + j],         w_hh1[(64 + uu) * 64 + j],
                                      w_hh1[(128 + uu) * 64 + j], w_hh1[(192 + uu) * 64 + j]);
    }
    // zero initial hidden state (buffer 0)
    for (int e = tid; e < 64 * BT; e += NTHR) { h0s[e] = 0.f; h1s[e] = 0.f; }

    // per-thread invariant constants (biases & input weights for unit u, duplicated pairs)
    ull bias0p[4], bias1p[4], wih0p[4];
#pragma unroll
    for (int g = 0; g < 4; g++) {
        float v0 = b_ih0[g * 64 + u] + b_hh0[g * 64 + u];
        float v1 = b_ih1[g * 64 + u] + b_hh1[g * 64 + u];
        float wi = w_ih0[g * 64 + u];   // INPUT_SIZE == 1
        bias0p[g] = pk2(v0, v0);
        bias1p[g] = pk2(v1, v1);
        wih0p[g]  = pk2(wi, wi);
    }

    float c0[8], c1[8];
#pragma unroll
    for (int i = 0; i < 8; i++) { c0[i] = 0.f; c1[i] = 0.f; }

    __syncthreads();

    int cur = 0;
    for (int t = 0; t < SS; t++) {
        // refill x staging chunk every XCH steps
        if ((t & (XCH - 1)) == 0) {
            __syncthreads();
            for (int e = tid; e < BT * XCH; e += NTHR) {
                int b = e >> 7, tc = e & (XCH - 1);  // lanes sweep tc -> coalesced
                xs[tc * BT + b] = x[(size_t)(b0 + b) * SS + t + tc];
            }
            __syncthreads();
        }

        const float* h0c = h0s + cur * 64 * BT;
        const float* h1c = h1s + cur * 64 * BT;
        float* h0n = h0s + (cur ^ 1) * 64 * BT;
        float* h1n = h1s + (cur ^ 1) * 64 * BT;

        ull a[4][4];
        float hv[8];

        // ================= layer 0 =================
        {
            const ulonglong2* xp = (const ulonglong2*)(xs + (t & (XCH - 1)) * BT + pb0);
            ulonglong2 xa = xp[0], xb = xp[1];
#pragma unroll
            for (int g = 0; g < 4; g++) {
                a[g][0] = bias0p[g]; a[g][1] = bias0p[g];
                a[g][2] = bias0p[g]; a[g][3] = bias0p[g];
                fma2(a[g][0], wih0p[g], xa.x); fma2(a[g][1], wih0p[g], xa.y);
                fma2(a[g][2], wih0p[g], xb.x); fma2(a[g][3], wih0p[g], xb.y);
            }
            mac64(a, W0 + u, h0c, pb0);
        }
        cell_update(a, c0, hv);
        *(float4*)(h0n + u * BT + pb0)     = make_float4(hv[0], hv[1], hv[2], hv[3]);
        *(float4*)(h0n + u * BT + pb0 + 4) = make_float4(hv[4], hv[5], hv[6], hv[7]);
        __syncthreads();   // h0(t) visible to all

        // ================= layer 1 =================
#pragma unroll
        for (int g = 0; g < 4; g++) {
            a[g][0] = bias1p[g]; a[g][1] = bias1p[g];
            a[g][2] = bias1p[g]; a[g][3] = bias1p[g];
        }
        mac64(a, W1 + u, h0n, pb0);  // input projection from new h0
        mac64(a, W2 + u, h1c, pb0);  // recurrent term from old h1
        cell_update(a, c1, hv);
        *(float4*)(h1n + u * BT + pb0)     = make_float4(hv[0], hv[1], hv[2], hv[3]);
        *(float4*)(h1n + u * BT + pb0 + 4) = make_float4(hv[4], hv[5], hv[6], hv[7]);
        __syncthreads();   // h1(t) visible; buffers safe to flip

        cur ^= 1;
    }

    // ================= final projection: out = h1(last) @ fc_w^T + fc_b =========
    const float* hf = h1s + cur * 64 * BT;
    for (int idx = tid; idx < BT * OUTN; idx += NTHR) {
        int b = idx / OUTN, o = idx - b * OUTN;
        float s = fc_b[o];
#pragma unroll 16
        for (int uu = 0; uu < 64; uu++)
            s += hf[uu * BT + b] * fc_w[o * 64 + uu];
        out[(size_t)(b0 + b) * OUTN + o] = s;
    }
}

extern "C" void kernel_launch(void* const* d_in, const int* in_sizes, int n_in,
                              void* d_out, int out_size) {
    (void)in_sizes; (void)n_in; (void)out_size;
    const float* x     = (const float*)d_in[0];
    const float* w_ih0 = (const float*)d_in[1];
    const float* w_hh0 = (const float*)d_in[2];
    const float* b_ih0 = (const float*)d_in[3];
    const float* b_hh0 = (const float*)d_in[4];
    const float* w_ih1 = (const float*)d_in[5];
    const float* w_hh1 = (const float*)d_in[6];
    const float* b_ih1 = (const float*)d_in[7];
    const float* b_hh1 = (const float*)d_in[8];
    const float* fc_w  = (const float*)d_in[9];
    const float* fc_b  = (const float*)d_in[10];

    size_t smem = (size_t)(3 * 64 * 64 * 4 + 2 * 64 * BT * 2 + BT * XCH) * sizeof(float);
    cudaFuncSetAttribute(lstm2_kernel, cudaFuncAttributeMaxDynamicSharedMemorySize, (int)smem);
    lstm2_kernel<<<CTAS, NTHR, smem>>>(x, w_ih0, w_hh0, b_ih0, b_hh0,
                                       w_ih1, w_hh1, b_ih1, b_hh1,
                                       fc_w, fc_b, (float*)d_out);
}